// round 10
// baseline (speedup 1.0000x reference)
#include <cuda_runtime.h>
#include <math.h>

#define D 512
#define NBLOCKS 1184         // 148 SMs x 8 CTAs: one full resident wave
#define BLK 256
#define WARPS_PER_BLK (BLK / 32)
#define EPSN (1e-13f + 1e-14f)

__device__ float g_partial[NBLOCKS];
__device__ unsigned int g_count;  // zero-init; last block wraps it back to 0

__device__ __forceinline__ void fma_chunk(const float4* a, const float4* b,
                                          float& dot, float& ss, float& ii) {
#pragma unroll
    for (int j = 0; j < 4; j++) {
        dot += a[j].x * b[j].x + a[j].y * b[j].y + a[j].z * b[j].z + a[j].w * b[j].w;
        ss  += a[j].x * a[j].x + a[j].y * a[j].y + a[j].z * a[j].z + a[j].w * a[j].w;
        ii  += b[j].x * b[j].x + b[j].y * b[j].y + b[j].z * b[j].z + b[j].w * b[j].w;
    }
}

__global__ __launch_bounds__(BLK, 8) void rowcos_fused_kernel(const float* __restrict__ s,
                                                              const float* __restrict__ im,
                                                              float* __restrict__ out,
                                                              int N) {
    const int lane = threadIdx.x & 31;
    const int g    = lane >> 3;   // 8-lane group id (0..3)
    const int l8   = lane & 7;    // lane within group
    const int gwarp  = (blockIdx.x * BLK + threadIdx.x) >> 5;
    const int nwarps = (gridDim.x * BLK) >> 5;

    // Row-granular balanced partition: warp w owns [w*N/nwarps, (w+1)*N/nwarps).
    // For N=65536, nwarps=9472 -> 6 or 7 rows per warp (<=1 row imbalance),
    // instead of the 4-row-tile grid-stride's 2:1 (8 vs 4 rows) imbalance.
    const int row_start = (int)(((long long)gwarp * N) / nwarps);
    const int row_end   = (int)(((long long)(gwarp + 1) * N) / nwarps);
    const int cnt       = row_end - row_start;
    const int n_it      = (cnt + 3) >> 2;   // uniform across the warp

    float acc = 0.0f;

    for (int it = 0; it < n_it; it++) {
        const int r = row_start + it * 4 + g;
        const bool valid = (r < row_end);

        float dot = 0.f, ss = 0.f, ii = 0.f;

        if (valid) {
            const float4* sp = reinterpret_cast<const float4*>(s + (size_t)r * D);
            const float4* ip = reinterpret_cast<const float4*>(im + (size_t)r * D);

            float4 aA[4], bA[4], aB[4], bB[4];
#pragma unroll
            for (int j = 0; j < 4; j++) { aA[j] = sp[l8 + j * 8];        bA[j] = ip[l8 + j * 8]; }
#pragma unroll
            for (int j = 0; j < 4; j++) { aB[j] = sp[l8 + (4 + j) * 8];  bB[j] = ip[l8 + (4 + j) * 8]; }

            fma_chunk(aA, bA, dot, ss, ii);
#pragma unroll
            for (int j = 0; j < 4; j++) { aA[j] = sp[l8 + (8 + j) * 8];  bA[j] = ip[l8 + (8 + j) * 8]; }

            fma_chunk(aB, bB, dot, ss, ii);
#pragma unroll
            for (int j = 0; j < 4; j++) { aB[j] = sp[l8 + (12 + j) * 8]; bB[j] = ip[l8 + (12 + j) * 8]; }

            fma_chunk(aA, bA, dot, ss, ii);
            fma_chunk(aB, bB, dot, ss, ii);
        }

        // All 32 lanes participate (invalid groups carry zeros).
#pragma unroll
        for (int off = 4; off > 0; off >>= 1) {
            dot += __shfl_xor_sync(0xffffffffu, dot, off);
            ss  += __shfl_xor_sync(0xffffffffu, ss,  off);
            ii  += __shfl_xor_sync(0xffffffffu, ii,  off);
        }

        if (valid && l8 == 0) {
            // eps (1.1e-13) negligible vs sqrt(ss) ~ 22.6; rsqrt avoids the div
            acc -= dot * rsqrtf(ss) * rsqrtf(ii);
        }
    }

    // acc nonzero only on lanes 0/8/16/24: fold with two butterflies.
    acc += __shfl_xor_sync(0xffffffffu, acc, 16);
    acc += __shfl_xor_sync(0xffffffffu, acc, 8);

    __shared__ float wsum[WARPS_PER_BLK];
    if (lane == 0) wsum[threadIdx.x >> 5] = acc;
    __syncthreads();

    __shared__ bool is_last;
    if (threadIdx.x == 0) {
        float bsum = 0.0f;
#pragma unroll
        for (int w = 0; w < WARPS_PER_BLK; w++) bsum += wsum[w];
        g_partial[blockIdx.x] = bsum;
        __threadfence();
        unsigned int done = atomicInc(&g_count, NBLOCKS - 1);  // wraps to 0 at last block
        is_last = (done == NBLOCKS - 1);
    }
    __syncthreads();

    if (is_last) {
        // Final sum of NBLOCKS partials: fixed-order strided accumulate,
        // warp butterflies, then an 8-value cross-warp fold.
        float v = 0.0f;
        for (int i = threadIdx.x; i < NBLOCKS; i += BLK) v += g_partial[i];
#pragma unroll
        for (int off = 16; off > 0; off >>= 1)
            v += __shfl_xor_sync(0xffffffffu, v, off);

        __shared__ float fsum[WARPS_PER_BLK];
        if (lane == 0) fsum[threadIdx.x >> 5] = v;
        __syncthreads();

        if (threadIdx.x == 0) {
            float t = 0.0f;
#pragma unroll
            for (int w = 0; w < WARPS_PER_BLK; w++) t += fsum[w];
            out[0] = t;
        }
    }
}

extern "C" void kernel_launch(void* const* d_in, const int* in_sizes, int n_in,
                              void* d_out, int out_size) {
    const float* s  = (const float*)d_in[0];
    const float* im = (const float*)d_in[1];
    const int N = in_sizes[0] / D;

    rowcos_fused_kernel<<<NBLOCKS, BLK>>>(s, im, (float*)d_out, N);
}

// round 11
// speedup vs baseline: 1.1176x; 1.1176x over previous
#include <cuda_runtime.h>
#include <math.h>

#define D 512
#define NBLOCKS 1184         // 148 SMs x 8 CTAs: one full resident wave
#define BLK 256
#define WARPS_PER_BLK (BLK / 32)
#define EPSN (1e-13f + 1e-14f)

__device__ float g_partial[NBLOCKS];
__device__ unsigned int g_count;  // zero-init; last block wraps it back to 0

__global__ __launch_bounds__(BLK, 8) void rowcos_fused_kernel(const float* __restrict__ s,
                                                              const float* __restrict__ im,
                                                              float* __restrict__ out,
                                                              int N) {
    const int lane = threadIdx.x & 31;
    const int gwarp  = (blockIdx.x * BLK + threadIdx.x) >> 5;
    const int nwarps = (gridDim.x * BLK) >> 5;

    float acc = 0.0f;

    // One row per warp per iteration. 65536 rows / 9472 warps = 6.92 ->
    // warps do 6 or 7 rows: only 1.2% tail-quantization loss (vs 13.8% for
    // 4-row tiles). launch_bounds(...,8) pins regs<=32 so all 64 warps/SM stay
    // resident; 16 warps/SMSP cover the depth-5 shuffle latency.
    for (int row = gwarp; row < N; row += nwarps) {
        const float4* sp = reinterpret_cast<const float4*>(s + (size_t)row * D);
        const float4* ip = reinterpret_cast<const float4*>(im + (size_t)row * D);

        // 128 float4 per row per array, 32 lanes -> 4 float4 each (8 loads).
        float4 a[4], b[4];
#pragma unroll
        for (int j = 0; j < 4; j++) {
            a[j] = sp[lane + j * 32];
            b[j] = ip[lane + j * 32];
        }

        float dot = 0.f, ss = 0.f, ii = 0.f;
#pragma unroll
        for (int j = 0; j < 4; j++) {
            dot += a[j].x * b[j].x + a[j].y * b[j].y + a[j].z * b[j].z + a[j].w * b[j].w;
            ss  += a[j].x * a[j].x + a[j].y * a[j].y + a[j].z * a[j].z + a[j].w * a[j].w;
            ii  += b[j].x * b[j].x + b[j].y * b[j].y + b[j].z * b[j].z + b[j].w * b[j].w;
        }

#pragma unroll
        for (int off = 16; off > 0; off >>= 1) {
            dot += __shfl_xor_sync(0xffffffffu, dot, off);
            ss  += __shfl_xor_sync(0xffffffffu, ss,  off);
            ii  += __shfl_xor_sync(0xffffffffu, ii,  off);
        }

        if (lane == 0) {
            // eps (1.1e-13) negligible vs sqrt(ss) ~ 22.6; rsqrt avoids the div
            acc -= dot * rsqrtf(ss) * rsqrtf(ii);
        }
    }

    // acc lives on lane 0 of each warp already.
    __shared__ float wsum[WARPS_PER_BLK];
    if (lane == 0) wsum[threadIdx.x >> 5] = acc;
    __syncthreads();

    __shared__ bool is_last;
    if (threadIdx.x == 0) {
        float bsum = 0.0f;
#pragma unroll
        for (int w = 0; w < WARPS_PER_BLK; w++) bsum += wsum[w];
        g_partial[blockIdx.x] = bsum;
        __threadfence();
        unsigned int done = atomicInc(&g_count, NBLOCKS - 1);  // wraps to 0 at last block
        is_last = (done == NBLOCKS - 1);
    }
    __syncthreads();

    if (is_last) {
        // Final sum of NBLOCKS partials: fixed-order strided accumulate,
        // warp butterflies, then an 8-value cross-warp fold.
        float v = 0.0f;
        for (int i = threadIdx.x; i < NBLOCKS; i += BLK) v += g_partial[i];
#pragma unroll
        for (int off = 16; off > 0; off >>= 1)
            v += __shfl_xor_sync(0xffffffffu, v, off);

        __shared__ float fsum[WARPS_PER_BLK];
        if (lane == 0) fsum[threadIdx.x >> 5] = v;
        __syncthreads();

        if (threadIdx.x == 0) {
            float t = 0.0f;
#pragma unroll
            for (int w = 0; w < WARPS_PER_BLK; w++) t += fsum[w];
            out[0] = t;
        }
    }
}

extern "C" void kernel_launch(void* const* d_in, const int* in_sizes, int n_in,
                              void* d_out, int out_size) {
    const float* s  = (const float*)d_in[0];
    const float* im = (const float*)d_in[1];
    const int N = in_sizes[0] / D;

    rowcos_fused_kernel<<<NBLOCKS, BLK>>>(s, im, (float*)d_out, N);
}

// round 12
// speedup vs baseline: 1.1285x; 1.0098x over previous
#include <cuda_runtime.h>
#include <math.h>
#include <stdint.h>

#define D 512
#define ROW_BYTES (D * 4)            // 2048
#define TILE_ROWS 16
#define TILE_BYTES (TILE_ROWS * ROW_BYTES)   // 32768 per tensor
#define STAGES 3
#define STAGE_BYTES (2 * TILE_BYTES)         // s + im per stage = 65536
#define SMEM_BYTES (STAGES * STAGE_BYTES)    // 196608
#define NBLOCKS 148
#define BLK 512                       // 16 warps == TILE_ROWS
#define WARPS_PER_BLK (BLK / 32)

__device__ float g_partial[NBLOCKS];
__device__ unsigned int g_count;     // zero-init; last block wraps it back to 0

__device__ __forceinline__ uint32_t smem_u32(const void* p) {
    uint32_t a;
    asm("{ .reg .u64 t; cvta.to.shared.u64 t, %1; cvt.u32.u64 %0, t; }"
        : "=r"(a) : "l"(p));
    return a;
}

__device__ __forceinline__ void mbar_init(uint32_t mbar, uint32_t cnt) {
    asm volatile("mbarrier.init.shared.b64 [%0], %1;" :: "r"(mbar), "r"(cnt) : "memory");
}
__device__ __forceinline__ void mbar_expect_tx(uint32_t mbar, uint32_t bytes) {
    asm volatile("mbarrier.arrive.expect_tx.shared.b64 _, [%0], %1;"
                 :: "r"(mbar), "r"(bytes) : "memory");
}
__device__ __forceinline__ void mbar_wait(uint32_t mbar, uint32_t parity) {
    uint32_t done;
    asm volatile(
        "{ .reg .pred p;\n"
        "  mbarrier.try_wait.parity.acquire.cta.shared::cta.b64 p, [%1], %2;\n"
        "  selp.b32 %0, 1, 0, p; }"
        : "=r"(done) : "r"(mbar), "r"(parity) : "memory");
    if (!done) {
        asm volatile(
            "{ .reg .pred P1;\n"
            "WAIT_%=:\n"
            "  mbarrier.try_wait.parity.acquire.cta.shared::cta.b64 P1, [%0], %1, 0x989680;\n"
            "  @P1 bra.uni DONE_%=;\n"
            "  bra.uni WAIT_%=;\n"
            "DONE_%=: }"
            :: "r"(mbar), "r"(parity) : "memory");
    }
}
__device__ __forceinline__ void bulk_ld(uint32_t dst_smem, const void* src, uint32_t bytes,
                                        uint32_t mbar) {
    asm volatile(
        "cp.async.bulk.shared::cta.global.mbarrier::complete_tx::bytes [%0], [%1], %2, [%3];"
        :: "r"(dst_smem), "l"(src), "r"(bytes), "r"(mbar) : "memory");
}

__global__ __launch_bounds__(BLK, 1) void rowcos_bulk_kernel(const float* __restrict__ s,
                                                             const float* __restrict__ im,
                                                             float* __restrict__ out,
                                                             int N) {
    extern __shared__ char dsm[];
    __shared__ __align__(8) uint64_t mbar_storage[STAGES];

    const int tid  = threadIdx.x;
    const int wid  = tid >> 5;
    const int lane = tid & 31;

    const uint32_t smem_base = smem_u32(dsm);
    const uint32_t mbar0 = smem_u32(&mbar_storage[0]);

    const int ntiles = N / TILE_ROWS;                    // 4096 for N=65536
    const long long c = blockIdx.x, G = gridDim.x;
    const int t0 = (int)(c * ntiles / G);
    const int t1 = (int)((c + 1) * ntiles / G);
    const int nt = t1 - t0;                              // 27 or 28 contiguous tiles

    if (tid < STAGES) mbar_init(mbar0 + tid * 8, 1);
    __syncthreads();

    // Prefill STAGES-1 tiles.
    if (tid == 0) {
        const int pre = (nt < STAGES - 1) ? nt : (STAGES - 1);
        for (int j = 0; j < pre; j++) {
            const uint32_t mb = mbar0 + j * 8;
            const uint32_t dst = smem_base + j * STAGE_BYTES;
            mbar_expect_tx(mb, STAGE_BYTES);
            bulk_ld(dst,              s  + (size_t)(t0 + j) * TILE_ROWS * D, TILE_BYTES, mb);
            bulk_ld(dst + TILE_BYTES, im + (size_t)(t0 + j) * TILE_ROWS * D, TILE_BYTES, mb);
        }
    }

    float acc = 0.0f;

    for (int i = 0; i < nt; i++) {
        // Issue tile i+STAGES-1 into the stage freed at iteration i-1.
        const int ia = i + STAGES - 1;
        if (ia < nt && tid == 0) {
            asm volatile("fence.proxy.async.shared::cta;" ::: "memory");
            const int sta = ia % STAGES;
            const uint32_t mb = mbar0 + sta * 8;
            const uint32_t dst = smem_base + sta * STAGE_BYTES;
            mbar_expect_tx(mb, STAGE_BYTES);
            bulk_ld(dst,              s  + (size_t)(t0 + ia) * TILE_ROWS * D, TILE_BYTES, mb);
            bulk_ld(dst + TILE_BYTES, im + (size_t)(t0 + ia) * TILE_ROWS * D, TILE_BYTES, mb);
        }

        const int st = i % STAGES;
        mbar_wait(mbar0 + st * 8, (uint32_t)((i / STAGES) & 1));

        // Warp w reduces row w of this 16-row tile, straight out of SMEM.
        const char* sb = dsm + st * STAGE_BYTES + wid * ROW_BYTES;
        const float4* sp = reinterpret_cast<const float4*>(sb);
        const float4* ip = reinterpret_cast<const float4*>(sb + TILE_BYTES);

        float4 a[4], b[4];
#pragma unroll
        for (int j = 0; j < 4; j++) {
            a[j] = sp[lane + j * 32];
            b[j] = ip[lane + j * 32];
        }
        float dot = 0.f, ss = 0.f, ii = 0.f;
#pragma unroll
        for (int j = 0; j < 4; j++) {
            dot += a[j].x * b[j].x + a[j].y * b[j].y + a[j].z * b[j].z + a[j].w * b[j].w;
            ss  += a[j].x * a[j].x + a[j].y * a[j].y + a[j].z * a[j].z + a[j].w * a[j].w;
            ii  += b[j].x * b[j].x + b[j].y * b[j].y + b[j].z * b[j].z + b[j].w * b[j].w;
        }
#pragma unroll
        for (int off = 16; off > 0; off >>= 1) {
            dot += __shfl_xor_sync(0xffffffffu, dot, off);
            ss  += __shfl_xor_sync(0xffffffffu, ss,  off);
            ii  += __shfl_xor_sync(0xffffffffu, ii,  off);
        }
        if (lane == 0) {
            // eps (1.1e-13) negligible vs sqrt(ss) ~ 22.6
            acc -= dot * rsqrtf(ss) * rsqrtf(ii);
        }

        __syncthreads();   // everyone done with stage st before it is overwritten
    }

    // Remainder rows (N % TILE_ROWS != 0) via direct loads — unused for N=65536.
    {
        const int first_rem = ntiles * TILE_ROWS;
        const int gwarp = blockIdx.x * WARPS_PER_BLK + wid;
        for (int row = first_rem + gwarp; row < N; row += NBLOCKS * WARPS_PER_BLK) {
            const float4* sp = reinterpret_cast<const float4*>(s + (size_t)row * D);
            const float4* ip = reinterpret_cast<const float4*>(im + (size_t)row * D);
            float dot = 0.f, ss = 0.f, ii = 0.f;
#pragma unroll
            for (int j = 0; j < 4; j++) {
                float4 a = sp[lane + j * 32];
                float4 b = ip[lane + j * 32];
                dot += a.x * b.x + a.y * b.y + a.z * b.z + a.w * b.w;
                ss  += a.x * a.x + a.y * a.y + a.z * a.z + a.w * a.w;
                ii  += b.x * b.x + b.y * b.y + b.z * b.z + b.w * b.w;
            }
#pragma unroll
            for (int off = 16; off > 0; off >>= 1) {
                dot += __shfl_xor_sync(0xffffffffu, dot, off);
                ss  += __shfl_xor_sync(0xffffffffu, ss,  off);
                ii  += __shfl_xor_sync(0xffffffffu, ii,  off);
            }
            if (lane == 0) acc -= dot * rsqrtf(ss) * rsqrtf(ii);
        }
    }

    // Block reduce (acc on lane 0 of each warp).
    __shared__ float wsum[WARPS_PER_BLK];
    if (lane == 0) wsum[wid] = acc;
    __syncthreads();

    __shared__ bool is_last;
    if (tid == 0) {
        float bsum = 0.0f;
#pragma unroll
        for (int w = 0; w < WARPS_PER_BLK; w++) bsum += wsum[w];
        g_partial[blockIdx.x] = bsum;
        __threadfence();
        unsigned int done = atomicInc(&g_count, NBLOCKS - 1);
        is_last = (done == NBLOCKS - 1);
    }
    __syncthreads();

    if (is_last && tid < 32) {
        float v = 0.0f;
        for (int i = lane; i < NBLOCKS; i += 32) v += g_partial[i];
#pragma unroll
        for (int off = 16; off > 0; off >>= 1)
            v += __shfl_xor_sync(0xffffffffu, v, off);
        if (lane == 0) out[0] = v;
    }
}

extern "C" void kernel_launch(void* const* d_in, const int* in_sizes, int n_in,
                              void* d_out, int out_size) {
    const float* s  = (const float*)d_in[0];
    const float* im = (const float*)d_in[1];
    const int N = in_sizes[0] / D;

    cudaFuncSetAttribute(rowcos_bulk_kernel,
                         cudaFuncAttributeMaxDynamicSharedMemorySize, SMEM_BYTES);
    rowcos_bulk_kernel<<<NBLOCKS, BLK, SMEM_BYTES>>>(s, im, (float*)d_out, N);
}